// round 17
// baseline (speedup 1.0000x reference)
#include <cuda_runtime.h>
#include <cuda_pipeline_primitives.h>
#include <math.h>

#define OUT_DIM 4096
#define DPC     16
#define NCOLS   (OUT_DIM * DPC)   // 65536
#define BATCH   512
#define NWARPS  8                 // warps per block; each warp = 32 windows
#define WSP     512               // staged floats per warp per array
#define WSP4    128               // float4 per warp per array

// Per-column boost factors, batch-invariant: computed once per launch.
__device__ float g_bf[NCOLS];

__global__ void bf_kernel(const float* __restrict__ duty_cycle,
                          const float* __restrict__ boost_strength) {
    int k = blockIdx.x * blockDim.x + threadIdx.x;
    const float td = (float)OUT_DIM / (float)NCOLS;  // 0.0625
    float bs = boost_strength[0];
    g_bf[k] = expf((td - duty_cycle[k]) * bs);
#if __CUDA_ARCH__ >= 900
    cudaTriggerProgrammaticLaunchCompletion();
#endif
}

__global__ void __launch_bounds__(256)
dkw_kernel(const float* __restrict__ x, float* __restrict__ out) {
    // Per-warp private staging: no block-level barriers anywhere.
    __shared__ float sx[NWARPS][WSP];
    __shared__ float sb[NWARPS][WSP];

    const int lane = threadIdx.x & 31;
    const int wrp  = threadIdx.x >> 5;
    const int g = blockIdx.x * NWARPS + wrp;   // global warp id
    const int b = g >> 7;                      // batch row (128 warps/row)
    const int r = g & 127;                     // warp within row

    const size_t rowoff = (size_t)b * NCOLS;
    const int W0 = 480 * r;                    // window span start (16B aligned)
    const int O0 = 512 * r;                    // output chunk start
    // Over-fetch proof: W0 + 512 <= 480*127 + 512 = 61472 < 65536.

    const float4* xw4 = reinterpret_cast<const float4*>(x + rowoff + W0);
    const float4* bf4 = reinterpret_cast<const float4*>(g_bf + W0);
    float4* sx4 = reinterpret_cast<float4*>(sx[wrp]);
    float4* sb4 = reinterpret_cast<float4*>(sb[wrp]);

    // ---- Async-stage x window (issued before PDL wait: prefetch overlap) ----
#pragma unroll
    for (int k = 0; k < 4; ++k)
        __pipeline_memcpy_async(&sx4[lane + 32 * k], &xw4[lane + 32 * k], 16);
    __pipeline_commit();

#if __CUDA_ARCH__ >= 900
    cudaGridDependencySynchronize();           // g_bf ready (PDL)
#endif

    // ---- Async-stage bf window ----
#pragma unroll
    for (int k = 0; k < 4; ++k)
        __pipeline_memcpy_async(&sb4[lane + 32 * k], &bf4[lane + 32 * k], 16);
    __pipeline_commit();

    __pipeline_wait_prior(0);
    __syncwarp();

    // ---- Argmax over window [15*lane, 15*lane+16): stride-15 LDS, conflict-free ----
    const float* px = sx[wrp] + 15 * lane;
    const float* pb = sb[wrp] + 15 * lane;
    float best = -INFINITY;
    int bj = 0;
#pragma unroll
    for (int j = 0; j < DPC; ++j) {
        float v = px[j] * pb[j];
        if (v > best) { best = v; bj = j; }
    }

    // ---- Masked output: bj exchanged via shfl (no SMEM, no extra sync) ----
    const float4* xc4 = reinterpret_cast<const float4*>(x + rowoff + O0);
    float4* o4 = reinterpret_cast<float4*>(out + rowoff + O0);
#pragma unroll
    for (int k = 0; k < 4; ++k) {
        int f  = lane + 32 * k;                // float4 index 0..127 in chunk
        int c  = f >> 2;                       // window index 0..31 within warp
        int j0 = (f & 3) << 2;                 // first j covered by this float4
        int bjc = __shfl_sync(0xffffffffu, bj, c);
        float4 xv = xc4[f];
        float4 v;
        v.x = (bjc == j0 + 0) ? xv.x : 0.0f;
        v.y = (bjc == j0 + 1) ? xv.y : 0.0f;
        v.z = (bjc == j0 + 2) ? xv.z : 0.0f;
        v.w = (bjc == j0 + 3) ? xv.w : 0.0f;
        o4[f] = v;
    }
}

extern "C" void kernel_launch(void* const* d_in, const int* in_sizes, int n_in,
                              void* d_out, int out_size) {
    const float* x  = (const float*)d_in[0];
    const float* dc = (const float*)d_in[1];
    const float* bs = (const float*)d_in[2];
    float* out = (float*)d_out;

    bf_kernel<<<NCOLS / 256, 256>>>(dc, bs);

    cudaLaunchConfig_t cfg = {};
    cfg.gridDim  = dim3(BATCH * OUT_DIM / (32 * NWARPS), 1, 1);   // 8192
    cfg.blockDim = dim3(32 * NWARPS, 1, 1);
    cfg.dynamicSmemBytes = 0;
    cfg.stream = 0;
    cudaLaunchAttribute attr[1];
    attr[0].id = cudaLaunchAttributeProgrammaticStreamSerialization;
    attr[0].val.programmaticStreamSerializationAllowed = 1;
    cfg.attrs = attr;
    cfg.numAttrs = 1;
    cudaLaunchKernelEx(&cfg, dkw_kernel, x, out);
}